// round 12
// baseline (speedup 1.0000x reference)
#include <cuda_runtime.h>
#include <math.h>

// TtMambaSSM (B=256, D=5120, R=160, N=16)
//   gemm1+reduce : partials + in-kernel reduction (device-wide handshake), TBC
//   gemm2        : delta = softplus(T @ W_dt + b)  (256x5120xK160)
//   elem         : out = x*(D + delta*BC) + sum_n exp(delta*A)*h0*Cp

typedef unsigned long long ull;

#define Bsz 256
#define Dsz 5120
#define NC  192
#define KSPLIT 40
#define G1BLOCKS (12 * KSPLIT)

__device__ float g_part[KSPLIT * Bsz * NC];
__device__ float g_TBC[Bsz * NC];
__device__ float g_delta[Bsz * Dsz];
__device__ int g_arrive;
__device__ int g_done;

__device__ __forceinline__ ull pack2(float lo, float hi) {
    ull r; asm("mov.b64 %0, {%1, %2};" : "=l"(r) : "f"(lo), "f"(hi)); return r;
}
__device__ __forceinline__ void ffma2(ull& d, ull a, ull b) {
    asm("fma.rn.f32x2 %0, %1, %2, %0;" : "+l"(d) : "l"(a), "l"(b));
}
__device__ __forceinline__ float2 unpack2(ull v) {
    float2 f; asm("mov.b64 {%0, %1}, %2;" : "=f"(f.x), "=f"(f.y) : "l"(v)); return f;
}

// virtual concatenated weight read: float4 at col j of [W_dt_low | W_B | W_C]
__device__ __forceinline__ float4 loadW(const float* __restrict__ Wlow,
                                        const float* __restrict__ WB,
                                        const float* __restrict__ WC,
                                        int k, int j) {
    if (j < 160) return *(const float4*)(Wlow + k * 160 + j);
    if (j < 176) return *(const float4*)(WB + k * 16 + (j - 160));
    return *(const float4*)(WC + k * 16 + (j - 176));
}

// ---------------- GEMM1 + fused reduce ----------------
// grid (12, 40): 4 m-tiles(64) x 3 n-tiles(64), k-chunk 128; 256 threads; 4x4 micro.
// All 480 blocks are simultaneously resident (122880 threads < chip capacity),
// so the device-wide handshake cannot deadlock.
__global__ void __launch_bounds__(256) gemm1_kernel(const float* __restrict__ x,
                                                    const float* __restrict__ Wlow,
                                                    const float* __restrict__ WB,
                                                    const float* __restrict__ WC)
{
    __shared__ float As[2][16][68];
    __shared__ float Bs[2][16][64];

    const int m0 = (blockIdx.x & 3) * 64;
    const int n0 = (blockIdx.x >> 2) * 64;
    const int k0 = blockIdx.y * 128;
    const int tid = threadIdx.x;
    const int ty = tid >> 4, tx = tid & 15;
    const int lm  = tid >> 2, lkq = (tid & 3) * 4;
    const int lkk = tid >> 4, lj4 = (tid & 15) * 4;

    ull acc[2][4];
    const ull z0 = pack2(0.0f, 0.0f);
#pragma unroll
    for (int p = 0; p < 2; p++)
#pragma unroll
        for (int j = 0; j < 4; j++) acc[p][j] = z0;

    float4 av = *(const float4*)(x + (m0 + lm) * Dsz + k0 + lkq);
    float4 bv = loadW(Wlow, WB, WC, k0 + lkk, n0 + lj4);
    As[0][lkq + 0][lm] = av.x; As[0][lkq + 1][lm] = av.y;
    As[0][lkq + 2][lm] = av.z; As[0][lkq + 3][lm] = av.w;
    *(float4*)&Bs[0][lkk][lj4] = bv;
    __syncthreads();

    for (int it = 0; it < 8; it++) {
        const int cur = it & 1;
        if (it < 7) {
            const int kb = k0 + (it + 1) * 16;
            av = *(const float4*)(x + (m0 + lm) * Dsz + kb + lkq);
            bv = loadW(Wlow, WB, WC, kb + lkk, n0 + lj4);
        }
#pragma unroll
        for (int kk = 0; kk < 16; kk++) {
            longlong2 ap = *(const longlong2*)&As[cur][kk][ty * 4];
            float4 b = *(const float4*)&Bs[cur][kk][tx * 4];
            const ull aP0 = (ull)ap.x, aP1 = (ull)ap.y;
            ull bd;
            bd = pack2(b.x, b.x); ffma2(acc[0][0], aP0, bd); ffma2(acc[1][0], aP1, bd);
            bd = pack2(b.y, b.y); ffma2(acc[0][1], aP0, bd); ffma2(acc[1][1], aP1, bd);
            bd = pack2(b.z, b.z); ffma2(acc[0][2], aP0, bd); ffma2(acc[1][2], aP1, bd);
            bd = pack2(b.w, b.w); ffma2(acc[0][3], aP0, bd); ffma2(acc[1][3], aP1, bd);
        }
        if (it < 7) {
            const int nxt = cur ^ 1;
            As[nxt][lkq + 0][lm] = av.x; As[nxt][lkq + 1][lm] = av.y;
            As[nxt][lkq + 2][lm] = av.z; As[nxt][lkq + 3][lm] = av.w;
            *(float4*)&Bs[nxt][lkk][lj4] = bv;
        }
        __syncthreads();
    }

    // coalesced partial store, then arrive
    float* dst = g_part + (size_t)blockIdx.y * (Bsz * NC);
#pragma unroll
    for (int p = 0; p < 2; p++) {
        float2 v0 = unpack2(acc[p][0]);
        float2 v1 = unpack2(acc[p][1]);
        float2 v2 = unpack2(acc[p][2]);
        float2 v3 = unpack2(acc[p][3]);
        const int row = m0 + ty * 4 + 2 * p;
        const int col = n0 + tx * 4;
        *(float4*)(dst + row * NC + col)       = make_float4(v0.x, v1.x, v2.x, v3.x);
        *(float4*)(dst + (row + 1) * NC + col) = make_float4(v0.y, v1.y, v2.y, v3.y);
    }
    __threadfence();
    if (tid == 0) atomicAdd(&g_arrive, 1);

    // ky==0 blocks (12 of them, 3072 threads) perform the reduction
    if (blockIdx.y == 0) {
        if (tid == 0) {
            while (atomicAdd(&g_arrive, 0) < G1BLOCKS) { }
        }
        __syncthreads();
        __threadfence();

        // 12288 float4 outputs / 3072 threads = 4 per thread
        const int t0 = blockIdx.x * 256 + tid;   // 0..3071
#pragma unroll
        for (int r = 0; r < 4; r++) {
            const int e4 = t0 + r * 3072;        // float4 index 0..12287
            float4 s = make_float4(0.f, 0.f, 0.f, 0.f);
#pragma unroll
            for (int k = 0; k < KSPLIT; k++) {
                float4 v = *(const float4*)(g_part + (size_t)k * (Bsz * NC) + e4 * 4);
                s.x += v.x; s.y += v.y; s.z += v.z; s.w += v.w;
            }
            *(float4*)(g_TBC + e4 * 4) = s;
        }
        __syncthreads();
        if (tid == 0) {
            __threadfence();
            int old = atomicAdd(&g_done, 1);
            if (old == 11) {            // last reducer resets counters for graph replay
                g_arrive = 0;
                g_done = 0;
            }
        }
    }
}

// ---------------- GEMM2: delta = softplus(T @ W_dt + b), double-buffered ----------------
// grid (80, 4): n-tiles(64) x m-tiles(64); 256 threads; 4x4 micro (m-paired acc)
__global__ void __launch_bounds__(256) gemm2_kernel(const float* __restrict__ Wdt,
                                                    const float* __restrict__ bias)
{
    __shared__ float As[2][16][68];
    __shared__ float Bs[2][16][64];
    __shared__ float bias_s[64];

    const int n0 = blockIdx.x * 64;
    const int m0 = blockIdx.y * 64;
    const int tid = threadIdx.x;
    const int ty = tid >> 4, tx = tid & 15;
    const int lm  = tid >> 2, lkq = (tid & 3) * 4;
    const int lkk = tid >> 4, lj4 = (tid & 15) * 4;

    if (tid < 64) bias_s[tid] = bias[n0 + tid];

    ull acc[2][4];
    const ull z0 = pack2(0.0f, 0.0f);
#pragma unroll
    for (int p = 0; p < 2; p++)
#pragma unroll
        for (int j = 0; j < 4; j++) acc[p][j] = z0;

    float4 av = *(const float4*)(g_TBC + (m0 + lm) * NC + lkq);
    float4 bv = *(const float4*)(Wdt + lkk * Dsz + n0 + lj4);
    As[0][lkq + 0][lm] = av.x; As[0][lkq + 1][lm] = av.y;
    As[0][lkq + 2][lm] = av.z; As[0][lkq + 3][lm] = av.w;
    *(float4*)&Bs[0][lkk][lj4] = bv;
    __syncthreads();

    for (int it = 0; it < 10; it++) {
        const int cur = it & 1;
        if (it < 9) {
            const int kb = (it + 1) * 16;
            av = *(const float4*)(g_TBC + (m0 + lm) * NC + kb + lkq);
            bv = *(const float4*)(Wdt + (kb + lkk) * Dsz + n0 + lj4);
        }
#pragma unroll
        for (int kk = 0; kk < 16; kk++) {
            longlong2 ap = *(const longlong2*)&As[cur][kk][ty * 4];
            float4 b = *(const float4*)&Bs[cur][kk][tx * 4];
            const ull aP0 = (ull)ap.x, aP1 = (ull)ap.y;
            ull bd;
            bd = pack2(b.x, b.x); ffma2(acc[0][0], aP0, bd); ffma2(acc[1][0], aP1, bd);
            bd = pack2(b.y, b.y); ffma2(acc[0][1], aP0, bd); ffma2(acc[1][1], aP1, bd);
            bd = pack2(b.z, b.z); ffma2(acc[0][2], aP0, bd); ffma2(acc[1][2], aP1, bd);
            bd = pack2(b.w, b.w); ffma2(acc[0][3], aP0, bd); ffma2(acc[1][3], aP1, bd);
        }
        if (it < 9) {
            const int nxt = cur ^ 1;
            As[nxt][lkq + 0][lm] = av.x; As[nxt][lkq + 1][lm] = av.y;
            As[nxt][lkq + 2][lm] = av.z; As[nxt][lkq + 3][lm] = av.w;
            *(float4*)&Bs[nxt][lkk][lj4] = bv;
        }
        __syncthreads();
    }
#pragma unroll
    for (int p = 0; p < 2; p++)
#pragma unroll
        for (int j = 0; j < 4; j++) {
            float2 v = unpack2(acc[p][j]);
            const int row = m0 + ty * 4 + 2 * p;
            const int col = n0 + tx * 4 + j;
            const float bb = bias_s[tx * 4 + j];
            float t0 = v.x + bb, t1 = v.y + bb;
            g_delta[row * Dsz + col]       = (t0 > 20.0f) ? t0 : log1pf(expf(t0));
            g_delta[(row + 1) * Dsz + col] = (t1 > 20.0f) ? t1 : log1pf(expf(t1));
        }
}

// ---------------- elem: out = x*(D + delta*BC) + sum_n exp(delta*A)*h0*Cp ----------------
// grid (20, 64): d-chunk 256, b-chunk 4. 256 threads; lane quad per d, 4 states/lane.
__global__ void __launch_bounds__(256) elem_kernel(const float* __restrict__ x,
                                                   const float* __restrict__ Ag,
                                                   const float* __restrict__ Dg,
                                                   const float* __restrict__ h0,
                                                   float* __restrict__ out)
{
    __shared__ float delta_s[4 * 256];
    __shared__ float y_s[4 * 256];
    __shared__ float D_s[256];
    __shared__ float Cp_s[4][16];
    __shared__ float BC_s[4];

    const int d0 = blockIdx.x * 256;
    const int b0 = blockIdx.y * 4;
    const int tid = threadIdx.x;

#pragma unroll
    for (int r = 0; r < 4; r++)
        delta_s[r * 256 + tid] = g_delta[(size_t)(b0 + r) * Dsz + d0 + tid];
    D_s[tid] = Dg[d0 + tid];
    if (tid < 64) {
        const int bb = tid >> 4, n = tid & 15;
        Cp_s[bb][n] = g_TBC[(b0 + bb) * NC + 176 + n];
    }
    __syncthreads();
    if (tid < 4) {
        float s = 0.0f;
#pragma unroll
        for (int n = 0; n < 16; n++)
            s += g_TBC[(b0 + tid) * NC + 160 + n] * Cp_s[tid][n];
        BC_s[tid] = s;
    }
    __syncthreads();

    const int nq = tid & 3;       // state quad 0..3
    const int dq = tid >> 2;      // local d 0..63

#pragma unroll
    for (int i = 0; i < 4; i++) {
        const int dloc = i * 64 + dq;
        const int d = d0 + dloc;
        const float4 Av = *(const float4*)(Ag + d * 16 + nq * 4);
        float4 hv[4];
#pragma unroll
        for (int b = 0; b < 4; b++)
            hv[b] = *(const float4*)(h0 + ((size_t)(b0 + b) * Dsz + d) * 16 + nq * 4);
#pragma unroll
        for (int b = 0; b < 4; b++) {
            const float delta = delta_s[b * 256 + dloc];
            const float* Cr = &Cp_s[b][nq * 4];
            float y = __expf(delta * Av.x) * (hv[b].x * Cr[0])
                    + __expf(delta * Av.y) * (hv[b].y * Cr[1])
                    + __expf(delta * Av.z) * (hv[b].z * Cr[2])
                    + __expf(delta * Av.w) * (hv[b].w * Cr[3]);
            y += __shfl_xor_sync(0xffffffffu, y, 1);
            y += __shfl_xor_sync(0xffffffffu, y, 2);
            if (nq == 0) y_s[b * 256 + dloc] = y;
        }
    }
    __syncthreads();

#pragma unroll
    for (int r = 0; r < 4; r++) {
        const int idx = r * 256 + tid;
        const size_t g = (size_t)(b0 + r) * Dsz + d0 + tid;
        out[g] = x[g] * (D_s[tid] + delta_s[idx] * BC_s[r]) + y_s[idx];
    }
}

extern "C" void kernel_launch(void* const* d_in, const int* in_sizes, int n_in,
                              void* d_out, int out_size) {
    const float* x    = (const float*)d_in[0];
    const float* Wlow = (const float*)d_in[1];
    const float* Wdt  = (const float*)d_in[2];
    const float* bdt  = (const float*)d_in[3];
    const float* WB   = (const float*)d_in[4];
    const float* WC   = (const float*)d_in[5];
    const float* A    = (const float*)d_in[6];
    const float* D    = (const float*)d_in[7];
    const float* h0   = (const float*)d_in[8];
    float* out = (float*)d_out;

    gemm1_kernel<<<dim3(12, KSPLIT), 256>>>(x, Wlow, WB, WC);
    gemm2_kernel<<<dim3(80, 4), 256>>>(Wdt, bdt);
    elem_kernel<<<dim3(20, 64), 256>>>(x, A, D, h0, out);
}

// round 14
// speedup vs baseline: 1.1183x; 1.1183x over previous
#include <cuda_runtime.h>
#include <math.h>

// TtMambaSSM (B=256, D=5120, R=160, N=16)
//   gemm1  : partials[ky] = x_chunk @ [W_dt_low|W_B|W_C]  (split-K=80, 960 blocks)
//   reduce : TBC = sum_ky partials[ky]
//   gemm2  : delta = softplus(T @ W_dt + b)  (256x5120xK160)
//   elem   : out = x*(D + delta*BC) + sum_n exp(delta*A)*h0*Cp

typedef unsigned long long ull;

#define Bsz 256
#define Dsz 5120
#define NC  192
#define KSPLIT 80
#define KCHUNK 64

__device__ float g_part[KSPLIT * Bsz * NC];
__device__ float g_TBC[Bsz * NC];
__device__ float g_delta[Bsz * Dsz];

__device__ __forceinline__ ull pack2(float lo, float hi) {
    ull r; asm("mov.b64 %0, {%1, %2};" : "=l"(r) : "f"(lo), "f"(hi)); return r;
}
__device__ __forceinline__ void ffma2(ull& d, ull a, ull b) {
    asm("fma.rn.f32x2 %0, %1, %2, %0;" : "+l"(d) : "l"(a), "l"(b));
}
__device__ __forceinline__ float2 unpack2(ull v) {
    float2 f; asm("mov.b64 {%0, %1}, %2;" : "=f"(f.x), "=f"(f.y) : "l"(v)); return f;
}

// virtual concatenated weight read: float4 at col j of [W_dt_low | W_B | W_C]
__device__ __forceinline__ float4 loadW(const float* __restrict__ Wlow,
                                        const float* __restrict__ WB,
                                        const float* __restrict__ WC,
                                        int k, int j) {
    if (j < 160) return *(const float4*)(Wlow + k * 160 + j);
    if (j < 176) return *(const float4*)(WB + k * 16 + (j - 160));
    return *(const float4*)(WC + k * 16 + (j - 176));
}

// ---------------- GEMM1: partials, split-K=80 ----------------
// grid (12, 80): 4 m-tiles(64) x 3 n-tiles(64), k-chunk 64; 256 threads; 4x4 micro
__global__ void __launch_bounds__(256) gemm1_kernel(const float* __restrict__ x,
                                                    const float* __restrict__ Wlow,
                                                    const float* __restrict__ WB,
                                                    const float* __restrict__ WC)
{
    __shared__ float As[2][16][68];
    __shared__ float Bs[2][16][64];

    const int m0 = (blockIdx.x & 3) * 64;
    const int n0 = (blockIdx.x >> 2) * 64;
    const int k0 = blockIdx.y * KCHUNK;
    const int tid = threadIdx.x;
    const int ty = tid >> 4, tx = tid & 15;
    const int lm  = tid >> 2, lkq = (tid & 3) * 4;
    const int lkk = tid >> 4, lj4 = (tid & 15) * 4;

    ull acc[2][4];
    const ull z0 = pack2(0.0f, 0.0f);
#pragma unroll
    for (int p = 0; p < 2; p++)
#pragma unroll
        for (int j = 0; j < 4; j++) acc[p][j] = z0;

    float4 av = *(const float4*)(x + (m0 + lm) * Dsz + k0 + lkq);
    float4 bv = loadW(Wlow, WB, WC, k0 + lkk, n0 + lj4);
    As[0][lkq + 0][lm] = av.x; As[0][lkq + 1][lm] = av.y;
    As[0][lkq + 2][lm] = av.z; As[0][lkq + 3][lm] = av.w;
    *(float4*)&Bs[0][lkk][lj4] = bv;
    __syncthreads();

#pragma unroll
    for (int it = 0; it < KCHUNK / 16; it++) {
        const int cur = it & 1;
        if (it < KCHUNK / 16 - 1) {
            const int kb = k0 + (it + 1) * 16;
            av = *(const float4*)(x + (m0 + lm) * Dsz + kb + lkq);
            bv = loadW(Wlow, WB, WC, kb + lkk, n0 + lj4);
        }
#pragma unroll
        for (int kk = 0; kk < 16; kk++) {
            longlong2 ap = *(const longlong2*)&As[cur][kk][ty * 4];
            float4 b = *(const float4*)&Bs[cur][kk][tx * 4];
            const ull aP0 = (ull)ap.x, aP1 = (ull)ap.y;
            ull bd;
            bd = pack2(b.x, b.x); ffma2(acc[0][0], aP0, bd); ffma2(acc[1][0], aP1, bd);
            bd = pack2(b.y, b.y); ffma2(acc[0][1], aP0, bd); ffma2(acc[1][1], aP1, bd);
            bd = pack2(b.z, b.z); ffma2(acc[0][2], aP0, bd); ffma2(acc[1][2], aP1, bd);
            bd = pack2(b.w, b.w); ffma2(acc[0][3], aP0, bd); ffma2(acc[1][3], aP1, bd);
        }
        if (it < KCHUNK / 16 - 1) {
            const int nxt = cur ^ 1;
            As[nxt][lkq + 0][lm] = av.x; As[nxt][lkq + 1][lm] = av.y;
            As[nxt][lkq + 2][lm] = av.z; As[nxt][lkq + 3][lm] = av.w;
            *(float4*)&Bs[nxt][lkk][lj4] = bv;
        }
        __syncthreads();
    }

    // coalesced partial store, no atomics
    float* dst = g_part + (size_t)blockIdx.y * (Bsz * NC);
#pragma unroll
    for (int p = 0; p < 2; p++) {
        float2 v0 = unpack2(acc[p][0]);
        float2 v1 = unpack2(acc[p][1]);
        float2 v2 = unpack2(acc[p][2]);
        float2 v3 = unpack2(acc[p][3]);
        const int row = m0 + ty * 4 + 2 * p;
        const int col = n0 + tx * 4;
        *(float4*)(dst + row * NC + col)       = make_float4(v0.x, v1.x, v2.x, v3.x);
        *(float4*)(dst + (row + 1) * NC + col) = make_float4(v0.y, v1.y, v2.y, v3.y);
    }
}

// ---------------- reduce: TBC = sum over 80 slices ----------------
__global__ void __launch_bounds__(256) reduce_kernel() {
    const int e = blockIdx.x * 256 + threadIdx.x;   // 0..49151
    float s0 = 0.f, s1 = 0.f, s2 = 0.f, s3 = 0.f;
#pragma unroll
    for (int k = 0; k < KSPLIT; k += 4) {
        s0 += g_part[(k + 0) * (Bsz * NC) + e];
        s1 += g_part[(k + 1) * (Bsz * NC) + e];
        s2 += g_part[(k + 2) * (Bsz * NC) + e];
        s3 += g_part[(k + 3) * (Bsz * NC) + e];
    }
    g_TBC[e] = (s0 + s1) + (s2 + s3);
}

// ---------------- GEMM2: delta = softplus(T @ W_dt + b), double-buffered ----------------
// grid (80, 4): n-tiles(64) x m-tiles(64); 256 threads; 4x4 micro (m-paired acc)
__global__ void __launch_bounds__(256) gemm2_kernel(const float* __restrict__ Wdt,
                                                    const float* __restrict__ bias)
{
    __shared__ float As[2][16][68];
    __shared__ float Bs[2][16][64];
    __shared__ float bias_s[64];

    const int n0 = blockIdx.x * 64;
    const int m0 = blockIdx.y * 64;
    const int tid = threadIdx.x;
    const int ty = tid >> 4, tx = tid & 15;
    const int lm  = tid >> 2, lkq = (tid & 3) * 4;
    const int lkk = tid >> 4, lj4 = (tid & 15) * 4;

    if (tid < 64) bias_s[tid] = bias[n0 + tid];

    ull acc[2][4];
    const ull z0 = pack2(0.0f, 0.0f);
#pragma unroll
    for (int p = 0; p < 2; p++)
#pragma unroll
        for (int j = 0; j < 4; j++) acc[p][j] = z0;

    float4 av = *(const float4*)(g_TBC + (m0 + lm) * NC + lkq);
    float4 bv = *(const float4*)(Wdt + lkk * Dsz + n0 + lj4);
    As[0][lkq + 0][lm] = av.x; As[0][lkq + 1][lm] = av.y;
    As[0][lkq + 2][lm] = av.z; As[0][lkq + 3][lm] = av.w;
    *(float4*)&Bs[0][lkk][lj4] = bv;
    __syncthreads();

    for (int it = 0; it < 10; it++) {
        const int cur = it & 1;
        if (it < 9) {
            const int kb = (it + 1) * 16;
            av = *(const float4*)(g_TBC + (m0 + lm) * NC + kb + lkq);
            bv = *(const float4*)(Wdt + (kb + lkk) * Dsz + n0 + lj4);
        }
#pragma unroll
        for (int kk = 0; kk < 16; kk++) {
            longlong2 ap = *(const longlong2*)&As[cur][kk][ty * 4];
            float4 b = *(const float4*)&Bs[cur][kk][tx * 4];
            const ull aP0 = (ull)ap.x, aP1 = (ull)ap.y;
            ull bd;
            bd = pack2(b.x, b.x); ffma2(acc[0][0], aP0, bd); ffma2(acc[1][0], aP1, bd);
            bd = pack2(b.y, b.y); ffma2(acc[0][1], aP0, bd); ffma2(acc[1][1], aP1, bd);
            bd = pack2(b.z, b.z); ffma2(acc[0][2], aP0, bd); ffma2(acc[1][2], aP1, bd);
            bd = pack2(b.w, b.w); ffma2(acc[0][3], aP0, bd); ffma2(acc[1][3], aP1, bd);
        }
        if (it < 9) {
            const int nxt = cur ^ 1;
            As[nxt][lkq + 0][lm] = av.x; As[nxt][lkq + 1][lm] = av.y;
            As[nxt][lkq + 2][lm] = av.z; As[nxt][lkq + 3][lm] = av.w;
            *(float4*)&Bs[nxt][lkk][lj4] = bv;
        }
        __syncthreads();
    }
#pragma unroll
    for (int p = 0; p < 2; p++)
#pragma unroll
        for (int j = 0; j < 4; j++) {
            float2 v = unpack2(acc[p][j]);
            const int row = m0 + ty * 4 + 2 * p;
            const int col = n0 + tx * 4 + j;
            const float bb = bias_s[tx * 4 + j];
            float t0 = v.x + bb, t1 = v.y + bb;
            g_delta[row * Dsz + col]       = (t0 > 20.0f) ? t0 : log1pf(expf(t0));
            g_delta[(row + 1) * Dsz + col] = (t1 > 20.0f) ? t1 : log1pf(expf(t1));
        }
}

// ---------------- elem: out = x*(D + delta*BC) + sum_n exp(delta*A)*h0*Cp ----------------
// grid (20, 64): d-chunk 256, b-chunk 4. 256 threads; lane quad per d, 4 states/lane.
__global__ void __launch_bounds__(256) elem_kernel(const float* __restrict__ x,
                                                   const float* __restrict__ Ag,
                                                   const float* __restrict__ Dg,
                                                   const float* __restrict__ h0,
                                                   float* __restrict__ out)
{
    __shared__ float delta_s[4 * 256];
    __shared__ float y_s[4 * 256];
    __shared__ float D_s[256];
    __shared__ float Cp_s[4][16];
    __shared__ float BC_s[4];

    const int d0 = blockIdx.x * 256;
    const int b0 = blockIdx.y * 4;
    const int tid = threadIdx.x;

#pragma unroll
    for (int r = 0; r < 4; r++)
        delta_s[r * 256 + tid] = g_delta[(size_t)(b0 + r) * Dsz + d0 + tid];
    D_s[tid] = Dg[d0 + tid];
    if (tid < 64) {
        const int bb = tid >> 4, n = tid & 15;
        Cp_s[bb][n] = g_TBC[(b0 + bb) * NC + 176 + n];
    }
    __syncthreads();
    if (tid < 4) {
        float s = 0.0f;
#pragma unroll
        for (int n = 0; n < 16; n++)
            s += g_TBC[(b0 + tid) * NC + 160 + n] * Cp_s[tid][n];
        BC_s[tid] = s;
    }
    __syncthreads();

    const int nq = tid & 3;       // state quad 0..3
    const int dq = tid >> 2;      // local d 0..63

#pragma unroll
    for (int i = 0; i < 4; i++) {
        const int dloc = i * 64 + dq;
        const int d = d0 + dloc;
        const float4 Av = *(const float4*)(Ag + d * 16 + nq * 4);
        float4 hv[4];
#pragma unroll
        for (int b = 0; b < 4; b++)
            hv[b] = *(const float4*)(h0 + ((size_t)(b0 + b) * Dsz + d) * 16 + nq * 4);
#pragma unroll
        for (int b = 0; b < 4; b++) {
            const float delta = delta_s[b * 256 + dloc];
            const float* Cr = &Cp_s[b][nq * 4];
            float y = __expf(delta * Av.x) * (hv[b].x * Cr[0])
                    + __expf(delta * Av.y) * (hv[b].y * Cr[1])
                    + __expf(delta * Av.z) * (hv[b].z * Cr[2])
                    + __expf(delta * Av.w) * (hv[b].w * Cr[3]);
            y += __shfl_xor_sync(0xffffffffu, y, 1);
            y += __shfl_xor_sync(0xffffffffu, y, 2);
            if (nq == 0) y_s[b * 256 + dloc] = y;
        }
    }
    __syncthreads();

#pragma unroll
    for (int r = 0; r < 4; r++) {
        const int idx = r * 256 + tid;
        const size_t g = (size_t)(b0 + r) * Dsz + d0 + tid;
        out[g] = x[g] * (D_s[tid] + delta_s[idx] * BC_s[r]) + y_s[idx];
    }
}

extern "C" void kernel_launch(void* const* d_in, const int* in_sizes, int n_in,
                              void* d_out, int out_size) {
    const float* x    = (const float*)d_in[0];
    const float* Wlow = (const float*)d_in[1];
    const float* Wdt  = (const float*)d_in[2];
    const float* bdt  = (const float*)d_in[3];
    const float* WB   = (const float*)d_in[4];
    const float* WC   = (const float*)d_in[5];
    const float* A    = (const float*)d_in[6];
    const float* D    = (const float*)d_in[7];
    const float* h0   = (const float*)d_in[8];
    float* out = (float*)d_out;

    gemm1_kernel<<<dim3(12, KSPLIT), 256>>>(x, Wlow, WB, WC);
    reduce_kernel<<<Bsz * NC / 256, 256>>>();
    gemm2_kernel<<<dim3(80, 4), 256>>>(Wdt, bdt);
    elem_kernel<<<dim3(20, 64), 256>>>(x, A, D, h0, out);
}

// round 17
// speedup vs baseline: 1.1915x; 1.0654x over previous
#include <cuda_runtime.h>
#include <cuda_bf16.h>
#include <cstdint>
#include <math.h>

// TtMambaSSM (B=256, D=5120, R=160, N=16)
//   gemm1  : partials[ky] = x @ [W_dt_low|W_B|W_C] via bf16-split mma.sync (tensor core)
//   reduce : TBC = sum_ky partials[ky]
//   gemm2  : delta = softplus(T @ W_dt + b)  (FFMA2 path, unchanged)
//   elem   : out = x*(D + delta*BC) + sum_n exp(delta*A)*h0*Cp  (unchanged)

typedef unsigned long long ull;

#define Bsz 256
#define Dsz 5120
#define NC  192
#define KSPLIT 40
#define KCHUNK 128

__device__ float g_part[KSPLIT * Bsz * NC];
__device__ float g_TBC[Bsz * NC];
__device__ float g_delta[Bsz * Dsz];

__device__ __forceinline__ ull pack2(float lo, float hi) {
    ull r; asm("mov.b64 %0, {%1, %2};" : "=l"(r) : "f"(lo), "f"(hi)); return r;
}
__device__ __forceinline__ void ffma2(ull& d, ull a, ull b) {
    asm("fma.rn.f32x2 %0, %1, %2, %0;" : "+l"(d) : "l"(a), "l"(b));
}
__device__ __forceinline__ float2 unpack2(ull v) {
    float2 f; asm("mov.b64 {%0, %1}, %2;" : "=f"(f.x), "=f"(f.y) : "l"(v)); return f;
}

// virtual concatenated weight read: float4 at col j of [W_dt_low | W_B | W_C]
__device__ __forceinline__ float4 loadW(const float* __restrict__ Wlow,
                                        const float* __restrict__ WB,
                                        const float* __restrict__ WC,
                                        int k, int j) {
    if (j < 160) return *(const float4*)(Wlow + k * 160 + j);
    if (j < 176) return *(const float4*)(WB + k * 16 + (j - 160));
    return *(const float4*)(WC + k * 16 + (j - 176));
}

__device__ __forceinline__ void ldsm4(unsigned& r0, unsigned& r1, unsigned& r2, unsigned& r3,
                                      unsigned addr) {
    asm volatile("ldmatrix.sync.aligned.m8n8.x4.shared.b16 {%0,%1,%2,%3}, [%4];"
                 : "=r"(r0), "=r"(r1), "=r"(r2), "=r"(r3) : "r"(addr));
}
__device__ __forceinline__ void ldsm2t(unsigned& r0, unsigned& r1, unsigned addr) {
    asm volatile("ldmatrix.sync.aligned.m8n8.x2.trans.shared.b16 {%0,%1}, [%2];"
                 : "=r"(r0), "=r"(r1) : "r"(addr));
}
__device__ __forceinline__ void mma_bf16(float* d, const unsigned* a, const unsigned* b) {
    asm volatile("mma.sync.aligned.m16n8k16.row.col.f32.bf16.bf16.f32 "
                 "{%0,%1,%2,%3}, {%4,%5,%6,%7}, {%8,%9}, {%0,%1,%2,%3};"
                 : "+f"(d[0]), "+f"(d[1]), "+f"(d[2]), "+f"(d[3])
                 : "r"(a[0]), "r"(a[1]), "r"(a[2]), "r"(a[3]),
                   "r"(b[0]), "r"(b[1]));
}

__device__ __forceinline__ void bf16_split(float v, __nv_bfloat16& h, __nv_bfloat16& l) {
    h = __float2bfloat16(v);
    l = __float2bfloat16(v - __bfloat162float(h));
}

// ---------------- GEMM1: bf16-split tensor-core, split-K=40 ----------------
// grid (12, 40): 4 m-tiles(64) x 3 n-tiles(64), k-chunk 128; 256 thr = 8 warps (2m x 4n)
__global__ void __launch_bounds__(256) gemm1_kernel(const float* __restrict__ x,
                                                    const float* __restrict__ Wlow,
                                                    const float* __restrict__ WB,
                                                    const float* __restrict__ WC)
{
    __shared__ __nv_bfloat16 Ah[64][24];   // rows padded to 48B (bank-clean LDSM)
    __shared__ __nv_bfloat16 Al[64][24];
    __shared__ __nv_bfloat16 Bh[16][72];   // rows padded to 144B
    __shared__ __nv_bfloat16 Bl[16][72];

    const int m0 = (blockIdx.x & 3) * 64;
    const int n0 = (blockIdx.x >> 2) * 64;
    const int k0 = blockIdx.y * KCHUNK;
    const int tid = threadIdx.x;
    const int lane = tid & 31, wid = tid >> 5;
    const int wm = (wid >> 2) * 32;     // warp m offset (0,32)
    const int wn = (wid & 3) * 16;      // warp n offset (0,16,32,48)

    float acc[2][2][4];
#pragma unroll
    for (int i = 0; i < 2; i++)
#pragma unroll
        for (int j = 0; j < 2; j++)
#pragma unroll
            for (int q = 0; q < 4; q++) acc[i][j][q] = 0.0f;

    // loader mapping
    const int am = tid >> 2, akq = (tid & 3) * 4;    // x: row 0..63, k quad
    const int bk = tid >> 4, bnq = (tid & 15) * 4;   // W: k row 0..15, n quad

    // ldmatrix addresses (per-thread constant)
    const unsigned aAddrH0 = (unsigned)__cvta_generic_to_shared(&Ah[wm + (lane & 15)][(lane >> 4) * 8]);
    const unsigned aAddrH1 = (unsigned)__cvta_generic_to_shared(&Ah[wm + 16 + (lane & 15)][(lane >> 4) * 8]);
    const unsigned aAddrL0 = (unsigned)__cvta_generic_to_shared(&Al[wm + (lane & 15)][(lane >> 4) * 8]);
    const unsigned aAddrL1 = (unsigned)__cvta_generic_to_shared(&Al[wm + 16 + (lane & 15)][(lane >> 4) * 8]);
    const unsigned bAddrH0 = (unsigned)__cvta_generic_to_shared(&Bh[lane & 15][wn]);
    const unsigned bAddrH1 = (unsigned)__cvta_generic_to_shared(&Bh[lane & 15][wn + 8]);
    const unsigned bAddrL0 = (unsigned)__cvta_generic_to_shared(&Bl[lane & 15][wn]);
    const unsigned bAddrL1 = (unsigned)__cvta_generic_to_shared(&Bl[lane & 15][wn + 8]);

    float4 av = *(const float4*)(x + (m0 + am) * Dsz + k0 + akq);
    float4 wv = loadW(Wlow, WB, WC, k0 + bk, n0 + bnq);

    for (int s = 0; s < KCHUNK / 16; s++) {
        // convert + store to smem
        {
            __nv_bfloat16 h0, h1, h2, h3, l0, l1, l2, l3;
            bf16_split(av.x, h0, l0); bf16_split(av.y, h1, l1);
            bf16_split(av.z, h2, l2); bf16_split(av.w, h3, l3);
            *(__nv_bfloat162*)&Ah[am][akq]     = __halves2bfloat162(h0, h1);
            *(__nv_bfloat162*)&Ah[am][akq + 2] = __halves2bfloat162(h2, h3);
            *(__nv_bfloat162*)&Al[am][akq]     = __halves2bfloat162(l0, l1);
            *(__nv_bfloat162*)&Al[am][akq + 2] = __halves2bfloat162(l2, l3);
            bf16_split(wv.x, h0, l0); bf16_split(wv.y, h1, l1);
            bf16_split(wv.z, h2, l2); bf16_split(wv.w, h3, l3);
            *(__nv_bfloat162*)&Bh[bk][bnq]     = __halves2bfloat162(h0, h1);
            *(__nv_bfloat162*)&Bh[bk][bnq + 2] = __halves2bfloat162(h2, h3);
            *(__nv_bfloat162*)&Bl[bk][bnq]     = __halves2bfloat162(l0, l1);
            *(__nv_bfloat162*)&Bl[bk][bnq + 2] = __halves2bfloat162(l2, l3);
        }
        __syncthreads();
        if (s < KCHUNK / 16 - 1) {
            const int kb = k0 + (s + 1) * 16;
            av = *(const float4*)(x + (m0 + am) * Dsz + kb + akq);
            wv = loadW(Wlow, WB, WC, kb + bk, n0 + bnq);
        }
        // ldmatrix fragments
        unsigned ah0[4], ah1[4], al0[4], al1[4];
        unsigned bh0[2], bh1[2], bl0[2], bl1[2];
        ldsm4(ah0[0], ah0[1], ah0[2], ah0[3], aAddrH0);
        ldsm4(ah1[0], ah1[1], ah1[2], ah1[3], aAddrH1);
        ldsm4(al0[0], al0[1], al0[2], al0[3], aAddrL0);
        ldsm4(al1[0], al1[1], al1[2], al1[3], aAddrL1);
        ldsm2t(bh0[0], bh0[1], bAddrH0);
        ldsm2t(bh1[0], bh1[1], bAddrH1);
        ldsm2t(bl0[0], bl0[1], bAddrL0);
        ldsm2t(bl1[0], bl1[1], bAddrL1);
        // 3-term split accumulate: hh + hl + lh
        mma_bf16(acc[0][0], ah0, bh0); mma_bf16(acc[0][1], ah0, bh1);
        mma_bf16(acc[1][0], ah1, bh0); mma_bf16(acc[1][1], ah1, bh1);
        mma_bf16(acc[0][0], ah0, bl0); mma_bf16(acc[0][1], ah0, bl1);
        mma_bf16(acc[1][0], ah1, bl0); mma_bf16(acc[1][1], ah1, bl1);
        mma_bf16(acc[0][0], al0, bh0); mma_bf16(acc[0][1], al0, bh1);
        mma_bf16(acc[1][0], al1, bh0); mma_bf16(acc[1][1], al1, bh1);
        __syncthreads();
    }

    // epilogue: d-frag mapping: rows g, g+8; cols (lane&3)*2, +1
    float* dst = g_part + (size_t)blockIdx.y * (Bsz * NC);
    const int gr = lane >> 2, c2 = (lane & 3) * 2;
#pragma unroll
    for (int mf = 0; mf < 2; mf++)
#pragma unroll
        for (int nf = 0; nf < 2; nf++) {
            const int row = m0 + wm + mf * 16 + gr;
            const int col = n0 + wn + nf * 8 + c2;
            *(float2*)(dst + row * NC + col)       = make_float2(acc[mf][nf][0], acc[mf][nf][1]);
            *(float2*)(dst + (row + 8) * NC + col) = make_float2(acc[mf][nf][2], acc[mf][nf][3]);
        }
}

// ---------------- reduce: TBC = sum over 40 slices ----------------
__global__ void __launch_bounds__(256) reduce_kernel() {
    const int e = blockIdx.x * 256 + threadIdx.x;   // 0..49151
    float s0 = 0.f, s1 = 0.f, s2 = 0.f, s3 = 0.f;
#pragma unroll
    for (int k = 0; k < KSPLIT; k += 4) {
        s0 += g_part[(k + 0) * (Bsz * NC) + e];
        s1 += g_part[(k + 1) * (Bsz * NC) + e];
        s2 += g_part[(k + 2) * (Bsz * NC) + e];
        s3 += g_part[(k + 3) * (Bsz * NC) + e];
    }
    g_TBC[e] = (s0 + s1) + (s2 + s3);
}

// ---------------- GEMM2: delta = softplus(T @ W_dt + b), double-buffered ----------------
// grid (80, 4): n-tiles(64) x m-tiles(64); 256 threads; 4x4 micro (m-paired acc)
__global__ void __launch_bounds__(256) gemm2_kernel(const float* __restrict__ Wdt,
                                                    const float* __restrict__ bias)
{
    __shared__ float As[2][16][68];
    __shared__ float Bs[2][16][64];
    __shared__ float bias_s[64];

    const int n0 = blockIdx.x * 64;
    const int m0 = blockIdx.y * 64;
    const int tid = threadIdx.x;
    const int ty = tid >> 4, tx = tid & 15;
    const int lm  = tid >> 2, lkq = (tid & 3) * 4;
    const int lkk = tid >> 4, lj4 = (tid & 15) * 4;

    if (tid < 64) bias_s[tid] = bias[n0 + tid];

    ull acc[2][4];
    const ull z0 = pack2(0.0f, 0.0f);
#pragma unroll
    for (int p = 0; p < 2; p++)
#pragma unroll
        for (int j = 0; j < 4; j++) acc[p][j] = z0;

    float4 av = *(const float4*)(g_TBC + (m0 + lm) * NC + lkq);
    float4 bv = *(const float4*)(Wdt + lkk * Dsz + n0 + lj4);
    As[0][lkq + 0][lm] = av.x; As[0][lkq + 1][lm] = av.y;
    As[0][lkq + 2][lm] = av.z; As[0][lkq + 3][lm] = av.w;
    *(float4*)&Bs[0][lkk][lj4] = bv;
    __syncthreads();

    for (int it = 0; it < 10; it++) {
        const int cur = it & 1;
        if (it < 9) {
            const int kb = (it + 1) * 16;
            av = *(const float4*)(g_TBC + (m0 + lm) * NC + kb + lkq);
            bv = *(const float4*)(Wdt + (kb + lkk) * Dsz + n0 + lj4);
        }
#pragma unroll
        for (int kk = 0; kk < 16; kk++) {
            longlong2 ap = *(const longlong2*)&As[cur][kk][ty * 4];
            float4 b = *(const float4*)&Bs[cur][kk][tx * 4];
            const ull aP0 = (ull)ap.x, aP1 = (ull)ap.y;
            ull bd;
            bd = pack2(b.x, b.x); ffma2(acc[0][0], aP0, bd); ffma2(acc[1][0], aP1, bd);
            bd = pack2(b.y, b.y); ffma2(acc[0][1], aP0, bd); ffma2(acc[1][1], aP1, bd);
            bd = pack2(b.z, b.z); ffma2(acc[0][2], aP0, bd); ffma2(acc[1][2], aP1, bd);
            bd = pack2(b.w, b.w); ffma2(acc[0][3], aP0, bd); ffma2(acc[1][3], aP1, bd);
        }
        if (it < 9) {
            const int nxt = cur ^ 1;
            As[nxt][lkq + 0][lm] = av.x; As[nxt][lkq + 1][lm] = av.y;
            As[nxt][lkq + 2][lm] = av.z; As[nxt][lkq + 3][lm] = av.w;
            *(float4*)&Bs[nxt][lkk][lj4] = bv;
        }
        __syncthreads();
    }
#pragma unroll
    for (int p = 0; p < 2; p++)
#pragma unroll
        for (int j = 0; j < 4; j++) {
            float2 v = unpack2(acc[p][j]);
            const int row = m0 + ty * 4 + 2 * p;
            const int col = n0 + tx * 4 + j;
            const float bb = bias_s[tx * 4 + j];
            float t0 = v.x + bb, t1 = v.y + bb;
            g_delta[row * Dsz + col]       = (t0 > 20.0f) ? t0 : log1pf(expf(t0));
            g_delta[(row + 1) * Dsz + col] = (t1 > 20.0f) ? t1 : log1pf(expf(t1));
        }
}

// ---------------- elem: out = x*(D + delta*BC) + sum_n exp(delta*A)*h0*Cp ----------------
// grid (20, 64): d-chunk 256, b-chunk 4. 256 threads; lane quad per d, 4 states/lane.
__global__ void __launch_bounds__(256) elem_kernel(const float* __restrict__ x,
                                                   const float* __restrict__ Ag,
                                                   const float* __restrict__ Dg,
                                                   const float* __restrict__ h0,
                                                   float* __restrict__ out)
{
    __shared__ float delta_s[4 * 256];
    __shared__ float y_s[4 * 256];
    __shared__ float D_s[256];
    __shared__ float Cp_s[4][16];
    __shared__ float BC_s[4];

    const int d0 = blockIdx.x * 256;
    const int b0 = blockIdx.y * 4;
    const int tid = threadIdx.x;

#pragma unroll
    for (int r = 0; r < 4; r++)
        delta_s[r * 256 + tid] = g_delta[(size_t)(b0 + r) * Dsz + d0 + tid];
    D_s[tid] = Dg[d0 + tid];
    if (tid < 64) {
        const int bb = tid >> 4, n = tid & 15;
        Cp_s[bb][n] = g_TBC[(b0 + bb) * NC + 176 + n];
    }
    __syncthreads();
    if (tid < 4) {
        float s = 0.0f;
#pragma unroll
        for (int n = 0; n < 16; n++)
            s += g_TBC[(b0 + tid) * NC + 160 + n] * Cp_s[tid][n];
        BC_s[tid] = s;
    }
    __syncthreads();

    const int nq = tid & 3;       // state quad 0..3
    const int dq = tid >> 2;      // local d 0..63

#pragma unroll
    for (int i = 0; i < 4; i++) {
        const int dloc = i * 64 + dq;
        const int d = d0 + dloc;
        const float4 Av = *(const float4*)(Ag + d * 16 + nq * 4);
        float4 hv[4];
#pragma unroll
        for (int b = 0; b < 4; b++)
            hv[b] = *(const float4*)(h0 + ((size_t)(b0 + b) * Dsz + d) * 16 + nq * 4);
#pragma unroll
        for (int b = 0; b < 4; b++) {
            const float delta = delta_s[b * 256 + dloc];
            const float* Cr = &Cp_s[b][nq * 4];
            float y = __expf(delta * Av.x) * (hv[b].x * Cr[0])
                    + __expf(delta * Av.y) * (hv[b].y * Cr[1])
                    + __expf(delta * Av.z) * (hv[b].z * Cr[2])
                    + __expf(delta * Av.w) * (hv[b].w * Cr[3]);
            y += __shfl_xor_sync(0xffffffffu, y, 1);
            y += __shfl_xor_sync(0xffffffffu, y, 2);
            if (nq == 0) y_s[b * 256 + dloc] = y;
        }
    }
    __syncthreads();

#pragma unroll
    for (int r = 0; r < 4; r++) {
        const int idx = r * 256 + tid;
        const size_t g = (size_t)(b0 + r) * Dsz + d0 + tid;
        out[g] = x[g] * (D_s[tid] + delta_s[idx] * BC_s[r]) + y_s[idx];
    }
}

extern "C" void kernel_launch(void* const* d_in, const int* in_sizes, int n_in,
                              void* d_out, int out_size) {
    const float* x    = (const float*)d_in[0];
    const float* Wlow = (const float*)d_in[1];
    const float* Wdt  = (const float*)d_in[2];
    const float* bdt  = (const float*)d_in[3];
    const float* WB   = (const float*)d_in[4];
    const float* WC   = (const float*)d_in[5];
    const float* A    = (const float*)d_in[6];
    const float* D    = (const float*)d_in[7];
    const float* h0   = (const float*)d_in[8];
    float* out = (float*)d_out;

    gemm1_kernel<<<dim3(12, KSPLIT), 256>>>(x, Wlow, WB, WC);
    reduce_kernel<<<Bsz * NC / 256, 256>>>();
    gemm2_kernel<<<dim3(80, 4), 256>>>(Wdt, bdt);
    elem_kernel<<<dim3(20, 64), 256>>>(x, A, D, h0, out);
}